// round 5
// baseline (speedup 1.0000x reference)
#include <cuda_runtime.h>
#include <math.h>

#define NB 16
#define CT 1024
#define CS 512
#define CM 512
#define HH 64
#define WW 64
#define HW 4096
#define NP 256
#define NA 256

// ---------------- scratch (device globals; no allocation) ----------------
__device__ float g_h[NB * CM * HW];        // conv1 output, relu applied (134 MB)
__device__ float g_heat[NB * HW];
__device__ float g_score[NB * HW];
__device__ int   g_idx[NB * NA];
__device__ float g_sampT[NB * NA * CT];
__device__ float g_sampS[NB * NA * CS];
__device__ float g_sal[NB * NA];
__device__ float g_ft[NB * NA * NP];
__device__ float g_fs[NB * NA * NP];
__device__ int   g_bd[NB * NA];
__device__ int   g_cnt[NB];
__device__ float g_gafd;
__device__ float g_abcd_b[NB];

// ---------------- f32x2 packed helpers (sm_103a FFMA2 path) ----------------
__device__ __forceinline__ unsigned long long pk2(float lo, float hi) {
    unsigned long long r;
    asm("mov.b64 %0, {%1,%2};" : "=l"(r) : "f"(lo), "f"(hi));
    return r;
}
__device__ __forceinline__ void upk2(unsigned long long v, float& lo, float& hi) {
    asm("mov.b64 {%0,%1}, %2;" : "=f"(lo), "=f"(hi) : "l"(v));
}
__device__ __forceinline__ void ffma2(unsigned long long& d, unsigned long long a,
                                      unsigned long long b) {
    asm("fma.rn.f32x2 %0, %1, %2, %0;" : "+l"(d) : "l"(a), "l"(b));
}

// ---------------- helpers ----------------
__device__ __forceinline__ float block_sum_256(float v, float* sh) {
#pragma unroll
    for (int o = 16; o; o >>= 1) v += __shfl_down_sync(0xffffffffu, v, o);
    __syncthreads();
    if ((threadIdx.x & 31) == 0) sh[threadIdx.x >> 5] = v;
    __syncthreads();
    if (threadIdx.x == 0) {
        float t = 0.f;
        for (int i = 0; i < 8; ++i) t += sh[i];
        sh[32] = t;
    }
    __syncthreads();
    return sh[32];
}

__device__ __forceinline__ float block_max_256(float v, float* sh) {
#pragma unroll
    for (int o = 16; o; o >>= 1) v = fmaxf(v, __shfl_down_sync(0xffffffffu, v, o));
    __syncthreads();
    if ((threadIdx.x & 31) == 0) sh[threadIdx.x >> 5] = v;
    __syncthreads();
    if (threadIdx.x == 0) {
        float t = sh[0];
        for (int i = 1; i < 8; ++i) t = fmaxf(t, sh[i]);
        sh[32] = t;
    }
    __syncthreads();
    return sh[32];
}

// JAX threefry2x32, matches jax._src.prng implementation exactly.
__device__ __forceinline__ void threefry2x32(unsigned k0, unsigned k1,
                                             unsigned x0, unsigned x1,
                                             unsigned& o0, unsigned& o1) {
    unsigned ks[3] = {k0, k1, k0 ^ k1 ^ 0x1BD11BDAu};
    x0 += ks[0];
    x1 += ks[1];
    const int R[5][4] = {{13, 15, 26, 6}, {17, 29, 16, 24}, {13, 15, 26, 6},
                         {17, 29, 16, 24}, {13, 15, 26, 6}};
#pragma unroll
    for (int g = 0; g < 5; ++g) {
#pragma unroll
        for (int q = 0; q < 4; ++q) {
            x0 += x1;
            int rr = R[g][q];
            x1 = (x1 << rr) | (x1 >> (32 - rr));
            x1 ^= x0;
        }
        x0 += ks[(g + 1) % 3];
        x1 += ks[(g + 2) % 3] + (unsigned)(g + 1);
    }
    o0 = x0;
    o1 = x1;
}

// ---------------- kernels ----------------
__global__ void reset_kernel() {
    int t = threadIdx.x;
    if (t == 0) g_gafd = 0.f;
    if (t < NB) g_abcd_b[t] = 0.f;
}

// conv1 3x3 pad1 + bias + relu. Tile: 64 co x (2 rows x 64 cols). 256 thr.
// Per thread: 8 co x 4 cols, accumulated as 4 co-PAIRS x 4 cols in f32x2.
__global__ __launch_bounds__(256) void conv1_kernel(const float* __restrict__ T,
                                                    const float* __restrict__ W1,
                                                    const float* __restrict__ b1) {
    __shared__ __align__(16) float sW[8][9][68];
    __shared__ float sI[8][4][68];
    int b = blockIdx.z, co0 = blockIdx.x * 64, y0 = blockIdx.y * 2;
    int tid = threadIdx.x;
    int r = tid >> 7, lane = tid & 127, cg = lane >> 4, c0 = lane & 15;

    unsigned long long acc[4][4];  // [co pair][col group]
#pragma unroll
    for (int i = 0; i < 4; ++i)
#pragma unroll
        for (int j = 0; j < 4; ++j) acc[i][j] = 0ull;

    for (int ci0 = 0; ci0 < CT; ci0 += 8) {
        __syncthreads();
        // weights: 64 co x 8 ci x 9 taps (coalesced: 72 contiguous floats per co)
        for (int idx = tid; idx < 64 * 72; idx += 256) {
            int co_l = idx / 72, k72 = idx % 72;
            int ci_l = k72 / 9, kk = k72 % 9;
            sW[ci_l][kk][co_l] =
                W1[(size_t)(co0 + co_l) * (CT * 9) + (size_t)(ci0 + ci_l) * 9 + kk];
        }
        // input: 8 ci x 4 rows (y0-1..y0+2) x 66 cols (x=-1..64), zero padded
        for (int idx = tid; idx < 8 * 4 * 66; idx += 256) {
            int col = idx % 66;
            int rest = idx / 66;
            int row = rest & 3, ci_l = rest >> 2;
            int x = col - 1, y = y0 - 1 + row;
            float v = 0.f;
            if (x >= 0 && x < WW && y >= 0 && y < HH)
                v = T[((size_t)(b * CT + ci0 + ci_l) * HH + y) * WW + x];
            sI[ci_l][row][col] = v;
        }
        __syncthreads();
#pragma unroll 1
        for (int ci = 0; ci < 8; ++ci) {
#pragma unroll
            for (int ky = 0; ky < 3; ++ky) {
                const float* rowp = sI[ci][r + ky];
#pragma unroll
                for (int kx = 0; kx < 3; ++kx) {
                    // weight pairs: adjacent co -> contiguous LDS.64
                    const float2* wp2 =
                        (const float2*)&sW[ci][ky * 3 + kx][cg * 8];
                    unsigned long long wp[4];
#pragma unroll
                    for (int i = 0; i < 4; ++i) {
                        float2 w2 = wp2[i];
                        wp[i] = pk2(w2.x, w2.y);
                    }
                    // input broadcast pairs
                    unsigned long long inp[4] = {
                        pk2(rowp[c0 + kx], rowp[c0 + kx]),
                        pk2(rowp[c0 + 16 + kx], rowp[c0 + 16 + kx]),
                        pk2(rowp[c0 + 32 + kx], rowp[c0 + 32 + kx]),
                        pk2(rowp[c0 + 48 + kx], rowp[c0 + 48 + kx])};
#pragma unroll
                    for (int i = 0; i < 4; ++i)
#pragma unroll
                        for (int j = 0; j < 4; ++j) ffma2(acc[i][j], wp[i], inp[j]);
                }
            }
        }
    }
    int row = y0 + r;
#pragma unroll
    for (int i = 0; i < 4; ++i) {
        int co = co0 + cg * 8 + 2 * i;
        float bias0 = b1[co], bias1 = b1[co + 1];
        float* o0 = &g_h[((size_t)(b * CM + co) * HH + row) * WW];
        float* o1 = &g_h[((size_t)(b * CM + co + 1) * HH + row) * WW];
#pragma unroll
        for (int j = 0; j < 4; ++j) {
            float vlo, vhi;
            upk2(acc[i][j], vlo, vhi);
            o0[c0 + 16 * j] = fmaxf(vlo + bias0, 0.f);
            o1[c0 + 16 * j] = fmaxf(vhi + bias1, 0.f);
        }
    }
}

// 1x1 conv over 512 channels + softplus; writes heatmap to scratch and d_out+3.
__global__ void heat_kernel(const float* __restrict__ w2,
                            const float* __restrict__ b2, float* __restrict__ out) {
    int b = blockIdx.x;
    int p = blockIdx.y * 256 + threadIdx.x;
    float acc = b2[0];
    const float* hp = g_h + (size_t)b * CM * HW + p;
#pragma unroll 4
    for (int c = 0; c < CM; ++c) acc += hp[(size_t)c * HW] * w2[c];
    float sp = fmaxf(acc, 0.f) + log1pf(expf(-fabsf(acc)));
    g_heat[b * HW + p] = sp;
    out[3 + b * HW + p] = sp;
}

// per-batch: normalize to prob, add JAX Gumbel noise -> score
// JAX >= 0.4.26 default: threefry_partitionable=True.
//   bits[i] = o0 ^ o1 where (o0,o1) = threefry2x32(key, (hi32(i), lo32(i)))
__global__ void score_kernel() {
    __shared__ float sh[33];
    int b = blockIdx.x;
    float s = 0.f;
    for (int p = threadIdx.x; p < HW; p += 256) s += g_heat[b * HW + p];
    float S = block_sum_256(s, sh);
    for (int p = threadIdx.x; p < HW; p += 256) {
        unsigned gi = (unsigned)(b * HW + p);
        unsigned o0, o1;
        threefry2x32(0u, 42u, 0u, gi, o0, o1);
        unsigned bits = o0 ^ o1;
        float f = __uint_as_float((bits >> 9) | 0x3f800000u) - 1.0f;
        float u = fmaxf(1e-8f, f * (1.0f - 1e-8f) + 1e-8f);
        float gum = -logf(-logf(u));
        g_score[gi] = logf(g_heat[gi] / (S + 1e-6f) + 1e-12f) + gum;
    }
}

// top-256 per batch via in-smem bitonic sort (ascending on negated key)
__global__ void topk_kernel() {
    __shared__ float key[HW];
    __shared__ int val[HW];
    int b = blockIdx.x;
    for (int i = threadIdx.x; i < HW; i += blockDim.x) {
        key[i] = -g_score[b * HW + i];
        val[i] = i;
    }
    for (int k = 2; k <= HW; k <<= 1)
        for (int j = k >> 1; j > 0; j >>= 1) {
            __syncthreads();
            for (int i = threadIdx.x; i < HW; i += blockDim.x) {
                int p = i ^ j;
                if (p > i) {
                    bool up = ((i & k) == 0);
                    float ki = key[i], kp = key[p];
                    if ((ki > kp) == up) {
                        key[i] = kp;
                        key[p] = ki;
                        int t = val[i];
                        val[i] = val[p];
                        val[p] = t;
                    }
                }
            }
        }
    __syncthreads();
    for (int i = threadIdx.x; i < NA; i += blockDim.x) g_idx[b * NA + i] = val[i];
}

// bilinear sample == 0.25 * sum of 4 pixels (r-1..r, c-1..c) with zero pad
__global__ void gather_kernel(const float* __restrict__ T,
                              const float* __restrict__ Sf) {
    int blk = blockIdx.x;
    int b = blk >> 8, n = blk & 255;
    int idx = g_idx[b * NA + n];
    int r = idx >> 6, c = idx & 63;
    bool rv = r > 0, cv = c > 0;
    int o11 = r * WW + c, o10 = o11 - 1, o01 = o11 - WW, o00 = o01 - 1;
    for (int ch = threadIdx.x; ch < CT; ch += blockDim.x) {
        const float* base = T + (size_t)(b * CT + ch) * HW;
        float s = base[o11];
        if (cv) s += base[o10];
        if (rv) {
            s += base[o01];
            if (cv) s += base[o00];
        }
        g_sampT[(size_t)(b * NA + n) * CT + ch] = 0.25f * s;
    }
    for (int ch = threadIdx.x; ch < CS; ch += blockDim.x) {
        const float* base = Sf + (size_t)(b * CS + ch) * HW;
        float s = base[o11];
        if (cv) s += base[o10];
        if (rv) {
            s += base[o01];
            if (cv) s += base[o00];
        }
        g_sampS[(size_t)(b * NA + n) * CS + ch] = 0.25f * s;
    }
    if (threadIdx.x == 0) {
        const float* base = g_heat + b * HW;
        float s = base[o11];
        if (cv) s += base[o10];
        if (rv) {
            s += base[o01];
            if (cv) s += base[o00];
        }
        g_sal[b * NA + n] = 0.25f * s;
    }
}

// [rows,C]@[C,256] + bias -> LayerNorm -> l2norm. 8 rows per block, thread = p.
template <int C>
__global__ void proj_kernel(const float* __restrict__ wmat,
                            const float* __restrict__ bias,
                            const float* __restrict__ gamma,
                            const float* __restrict__ beta) {
    __shared__ float sRow[8 * C];
    __shared__ float sh[33];
    const float* samp = (C == CT) ? g_sampT : g_sampS;
    float* outp = (C == CT) ? g_ft : g_fs;
    int a0 = blockIdx.x * 8;
    int p = threadIdx.x;
    for (int i = threadIdx.x; i < 8 * C; i += 256) sRow[i] = samp[(size_t)a0 * C + i];
    __syncthreads();
    float acc[8];
#pragma unroll
    for (int i = 0; i < 8; ++i) acc[i] = 0.f;
    for (int c = 0; c < C; ++c) {
        float w = wmat[(size_t)c * NP + p];
#pragma unroll
        for (int i = 0; i < 8; ++i) acc[i] += sRow[i * C + c] * w;
    }
    float bi = bias[p], ga = gamma[p], be = beta[p];
#pragma unroll 1
    for (int i = 0; i < 8; ++i) {
        float x = acc[i] + bi;
        float mu = block_sum_256(x, sh) * (1.0f / NP);
        float d = x - mu;
        float var = block_sum_256(d * d, sh) * (1.0f / NP);
        float y = d * rsqrtf(var + 1e-5f) * ga + be;
        float nrm = sqrtf(block_sum_256(y * y, sh));
        y = y / fmaxf(nrm, 1e-12f);
        outp[(size_t)(a0 + i) * NP + p] = y;
    }
}

__global__ void gafd_kernel() {
    __shared__ float sh[33];
    float s = 0.f;
    const int total = NB * NA * NP;
    for (int i = blockIdx.x * blockDim.x + threadIdx.x; i < total;
         i += gridDim.x * blockDim.x) {
        float d = g_fs[i] - g_ft[i];
        s += d * d;
    }
    float bs = block_sum_256(s, sh);
    if (threadIdx.x == 0) atomicAdd(&g_gafd, bs);
}

__global__ void bd_kernel() {
    __shared__ float sh[33];
    int b = blockIdx.x;
    float s = g_sal[b * NA + threadIdx.x];
    float mx = block_max_256(s, sh);
    int bd = (s > 0.6f * mx) ? 1 : 0;
    g_bd[b * NA + threadIdx.x] = bd;
    float cnt = block_sum_256((float)bd, sh);
    if (threadIdx.x == 0) g_cnt[b] = (int)(cnt + 0.5f);
}

// per bd-row: row_loss = logsumexp([pos, masked negs]) - pos
__global__ void abcd_kernel() {
    __shared__ float fsn[NP];
    __shared__ float sh[33];
    int blk = blockIdx.x;
    int b = blk >> 8, n = blk & 255;
    if (!g_bd[b * NA + n]) return;
    int t = threadIdx.x;
    float fv = g_fs[(size_t)(b * NA + n) * NP + t];
    float ftv = g_ft[(size_t)(b * NA + n) * NP + t];
    fsn[t] = fv;
    __syncthreads();
    float pos = block_sum_256(fv * ftv, sh) * 10.0f;  // /TAU
    const float4* fm = (const float4*)(g_fs + (size_t)(b * NA + t) * NP);
    float dm = 0.f;
#pragma unroll 4
    for (int q = 0; q < NP / 4; ++q) {
        float4 v = fm[q];
        dm += fsn[4 * q] * v.x + fsn[4 * q + 1] * v.y + fsn[4 * q + 2] * v.z +
              fsn[4 * q + 3] * v.w;
    }
    float val = g_bd[b * NA + t] ? -1e30f : dm * 10.0f;
    float mx = fmaxf(pos, block_max_256(val, sh));
    float e = (val < -1e29f) ? 0.f : expf(val - mx);
    float ssum = block_sum_256(e, sh) + expf(pos - mx);
    if (t == 0) atomicAdd(&g_abcd_b[b], mx + logf(ssum) - pos);
}

__global__ void final_kernel(float* __restrict__ out) {
    int t = threadIdx.x;
    float per = 0.f, valid = 0.f;
    if (t < NB) {
        int c = g_cnt[t];
        per = g_abcd_b[t] / fmaxf((float)c, 1.0f);
        valid = (c > 0 && c < NA) ? 1.0f : 0.0f;
    }
    float pv = per * valid;
#pragma unroll
    for (int o = 16; o; o >>= 1) {
        pv += __shfl_down_sync(0xffffffffu, pv, o);
        valid += __shfl_down_sync(0xffffffffu, valid, o);
    }
    if (t == 0) {
        float gafd = g_gafd * (1.0f / (NB * NA * NP));
        float abcd = (valid > 0.f) ? pv / valid : 0.f;
        out[0] = gafd + 0.5f * abcd;
        out[1] = gafd;
        out[2] = abcd;
    }
}

// ---------------- host launch ----------------
extern "C" void kernel_launch(void* const* d_in, const int* in_sizes, int n_in,
                              void* d_out, int out_size) {
    const float* T = (const float*)d_in[0];
    const float* Sf = (const float*)d_in[1];
    const float* w1 = (const float*)d_in[2];
    const float* b1 = (const float*)d_in[3];
    const float* w2 = (const float*)d_in[4];
    const float* b2 = (const float*)d_in[5];
    const float* tw = (const float*)d_in[6];
    const float* tb = (const float*)d_in[7];
    const float* tg = (const float*)d_in[8];
    const float* tbe = (const float*)d_in[9];
    const float* sw = (const float*)d_in[10];
    const float* sb = (const float*)d_in[11];
    const float* sg = (const float*)d_in[12];
    const float* sbe = (const float*)d_in[13];
    float* out = (float*)d_out;

    reset_kernel<<<1, 32>>>();
    conv1_kernel<<<dim3(8, 32, 16), 256>>>(T, w1, b1);
    heat_kernel<<<dim3(16, 16), 256>>>(w2, b2, out);
    score_kernel<<<16, 256>>>();
    topk_kernel<<<16, 512>>>();
    gather_kernel<<<NB * NA, 256>>>(T, Sf);
    proj_kernel<CT><<<512, 256>>>(tw, tb, tg, tbe);
    proj_kernel<CS><<<512, 256>>>(sw, sb, sg, sbe);
    gafd_kernel<<<256, 256>>>();
    bd_kernel<<<NB, 256>>>();
    abcd_kernel<<<NB * NA, 256>>>();
    final_kernel<<<1, 32>>>(out);
}

// round 7
// speedup vs baseline: 2.5129x; 2.5129x over previous
#include <cuda_runtime.h>
#include <cuda_bf16.h>
#include <math.h>
#include <stdint.h>

#define NB 16
#define CT 1024
#define CS 512
#define CM 512
#define HH 64
#define WW 64
#define HW 4096
#define NP 256
#define NA 256

// ---------------- scratch (device globals; no allocation) ----------------
__device__ float g_h[NB * CM * HW];   // conv1 output, relu applied (134 MB)
__device__ float g_heat[NB * HW];
__device__ float g_score[NB * HW];
__device__ int   g_idx[NB * NA];
__device__ float g_sampT[NB * NA * CT];
__device__ float g_sampS[NB * NA * CS];
__device__ float g_sal[NB * NA];
__device__ float g_ft[NB * NA * NP];
__device__ float g_fs[NB * NA * NP];
__device__ int   g_bd[NB * NA];
__device__ int   g_cnt[NB];
__device__ float g_gafd;
__device__ float g_abcd_b[NB];

// bf16 hi/lo split tensors for tensor-core conv
__device__ __align__(16) __nv_bfloat16 g_Thi[NB * HW * CT];      // [b][p][ci]
__device__ __align__(16) __nv_bfloat16 g_Tlo[NB * HW * CT];
__device__ __align__(16) __nv_bfloat16 g_Whi[9 * CM * CT];       // [tap][co][ci]
__device__ __align__(16) __nv_bfloat16 g_Wlo[9 * CM * CT];

// ---------------- sm_80-class PTX helpers (compile on compute_103) --------
__device__ __forceinline__ uint32_t smem_to_u32(const void* smem_ptr) {
    uint32_t addr;
    asm("{ .reg .u64 tmp; cvta.to.shared.u64 tmp, %1; cvt.u32.u64 %0, tmp; }"
        : "=r"(addr) : "l"(smem_ptr));
    return addr;
}
__device__ __forceinline__ void cp16(uint32_t dst, const void* src, bool ok) {
    int sz = ok ? 16 : 0;
    asm volatile("cp.async.cg.shared.global [%0], [%1], 16, %2;"
                 :: "r"(dst), "l"(src), "r"(sz) : "memory");
}
#define CP_COMMIT() asm volatile("cp.async.commit_group;" ::: "memory")
#define CP_WAIT1()  asm volatile("cp.async.wait_group 1;" ::: "memory")
#define CP_WAIT0()  asm volatile("cp.async.wait_group 0;" ::: "memory")

__device__ __forceinline__ void ldsm4(uint32_t* r, uint32_t addr) {
    asm volatile("ldmatrix.sync.aligned.m8n8.x4.shared.b16 {%0,%1,%2,%3}, [%4];"
                 : "=r"(r[0]), "=r"(r[1]), "=r"(r[2]), "=r"(r[3]) : "r"(addr));
}
__device__ __forceinline__ void mma16816(float* c, const uint32_t* a,
                                         uint32_t b0, uint32_t b1) {
    asm volatile(
        "mma.sync.aligned.m16n8k16.row.col.f32.bf16.bf16.f32 "
        "{%0,%1,%2,%3}, {%4,%5,%6,%7}, {%8,%9}, {%0,%1,%2,%3};"
        : "+f"(c[0]), "+f"(c[1]), "+f"(c[2]), "+f"(c[3])
        : "r"(a[0]), "r"(a[1]), "r"(a[2]), "r"(a[3]), "r"(b0), "r"(b1));
}

// ---------------- generic helpers ----------------
__device__ __forceinline__ float block_sum_256(float v, float* sh) {
#pragma unroll
    for (int o = 16; o; o >>= 1) v += __shfl_down_sync(0xffffffffu, v, o);
    __syncthreads();
    if ((threadIdx.x & 31) == 0) sh[threadIdx.x >> 5] = v;
    __syncthreads();
    if (threadIdx.x == 0) {
        float t = 0.f;
        for (int i = 0; i < 8; ++i) t += sh[i];
        sh[32] = t;
    }
    __syncthreads();
    return sh[32];
}

__device__ __forceinline__ float block_max_256(float v, float* sh) {
#pragma unroll
    for (int o = 16; o; o >>= 1) v = fmaxf(v, __shfl_down_sync(0xffffffffu, v, o));
    __syncthreads();
    if ((threadIdx.x & 31) == 0) sh[threadIdx.x >> 5] = v;
    __syncthreads();
    if (threadIdx.x == 0) {
        float t = sh[0];
        for (int i = 1; i < 8; ++i) t = fmaxf(t, sh[i]);
        sh[32] = t;
    }
    __syncthreads();
    return sh[32];
}

__device__ __forceinline__ void threefry2x32(unsigned k0, unsigned k1,
                                             unsigned x0, unsigned x1,
                                             unsigned& o0, unsigned& o1) {
    unsigned ks[3] = {k0, k1, k0 ^ k1 ^ 0x1BD11BDAu};
    x0 += ks[0];
    x1 += ks[1];
    const int R[5][4] = {{13, 15, 26, 6}, {17, 29, 16, 24}, {13, 15, 26, 6},
                         {17, 29, 16, 24}, {13, 15, 26, 6}};
#pragma unroll
    for (int g = 0; g < 5; ++g) {
#pragma unroll
        for (int q = 0; q < 4; ++q) {
            x0 += x1;
            int rr = R[g][q];
            x1 = (x1 << rr) | (x1 >> (32 - rr));
            x1 ^= x0;
        }
        x0 += ks[(g + 1) % 3];
        x1 += ks[(g + 2) % 3] + (unsigned)(g + 1);
    }
    o0 = x0;
    o1 = x1;
}

// ---------------- kernels ----------------
__global__ void reset_kernel() {
    int t = threadIdx.x;
    if (t == 0) g_gafd = 0.f;
    if (t < NB) g_abcd_b[t] = 0.f;
}

// transpose + bf16 split of teacher feat: T[b][ci][p] -> Thi/Tlo[b][p][ci]
__global__ void tprep_kernel(const float* __restrict__ T) {
    __shared__ float tile[32][33];
    int b = blockIdx.z, p0 = blockIdx.x * 32, c0 = blockIdx.y * 32;
    int tx = threadIdx.x, ty = threadIdx.y;
    for (int i = ty; i < 32; i += 8)
        tile[i][tx] = T[((size_t)(b * CT + c0 + i)) * HW + p0 + tx];
    __syncthreads();
    for (int i = ty; i < 32; i += 8) {
        float v = tile[tx][i];
        __nv_bfloat16 h = __float2bfloat16(v);
        float hf = __bfloat162float(h);
        size_t o = ((size_t)b * HW + p0 + i) * CT + c0 + tx;
        g_Thi[o] = h;
        g_Tlo[o] = __float2bfloat16(v - hf);
    }
}

// weights split: W1[co][ci][tap] -> Whi/Wlo[tap][co][ci]
__global__ void wprep_kernel(const float* __restrict__ W1) {
    int idx = blockIdx.x * blockDim.x + threadIdx.x;
    if (idx >= 9 * CM * CT) return;
    int ci = idx & (CT - 1);
    int rest = idx >> 10;
    int co = rest & (CM - 1);
    int tap = rest >> 9;
    float w = W1[((size_t)co * CT + ci) * 9 + tap];
    __nv_bfloat16 h = __float2bfloat16(w);
    float hf = __bfloat162float(h);
    g_Whi[idx] = h;
    g_Wlo[idx] = __float2bfloat16(w - hf);
}

// conv1 via mma.sync bf16x3 implicit GEMM.
// CTA: 128 pixels x 128 co. K loop: 9 taps x 16 chunks of 64 ci, x3 passes.
#define KB 64
#define ROWB 144                    // bytes per smem row (64 bf16 + 8 pad)
#define TEN_BYTES (128 * ROWB)      // 18432
#define STAGE_BYTES (4 * TEN_BYTES) // Ahi,Alo,Bhi,Blo = 73728
__global__ __launch_bounds__(256, 1)
void convmma_kernel(const float* __restrict__ b1) {
    extern __shared__ char dsm[];
    uint32_t sb = smem_to_u32(dsm);
    int tid = threadIdx.x, lane = tid & 31, wid = tid >> 5;
    int co0 = blockIdx.x * 128;
    int pixtile = blockIdx.y;
    int bb = blockIdx.z;
    int y0 = pixtile * 2, p0 = pixtile * 128;
    int wm = wid & 3, wn = wid >> 2;

    float acc[2][8][4];
#pragma unroll
    for (int i = 0; i < 2; ++i)
#pragma unroll
        for (int j = 0; j < 8; ++j)
#pragma unroll
            for (int k = 0; k < 4; ++k) acc[i][j][k] = 0.f;

    auto load_chunk = [&](int c, int s) {
        int tap = c >> 4, kc = c & 15;
        int dy = tap / 3 - 1, dx = tap % 3 - 1;
        int ci0 = kc * 64;
        uint32_t base = sb + (uint32_t)s * STAGE_BYTES;
        // A: 128 pixel rows x 64 ci, shifted + zero-masked
#pragma unroll
        for (int i = 0; i < 4; ++i) {
            int u = i * 256 + tid;
            int r = u >> 3, seg = u & 7;
            int ys = y0 + (r >> 6) + dy;
            int xs = (r & 63) + dx;
            bool ok = ((unsigned)ys < 64u) && ((unsigned)xs < 64u);
            int ysc = ok ? ys : 0, xsc = ok ? xs : 0;
            size_t g = ((size_t)(bb * HW + ysc * 64 + xsc)) * CT + ci0 + seg * 8;
            uint32_t off = (uint32_t)(r * ROWB + seg * 16);
            cp16(base + off, g_Thi + g, ok);
            cp16(base + TEN_BYTES + off, g_Tlo + g, ok);
        }
        // B: 128 co rows x 64 ci
#pragma unroll
        for (int i = 0; i < 4; ++i) {
            int u = i * 256 + tid;
            int r = u >> 3, seg = u & 7;
            size_t g = ((size_t)(tap * CM + co0 + r)) * CT + ci0 + seg * 8;
            uint32_t off = (uint32_t)(r * ROWB + seg * 16);
            cp16(base + 2 * TEN_BYTES + off, g_Whi + g, true);
            cp16(base + 3 * TEN_BYTES + off, g_Wlo + g, true);
        }
    };

    auto compute = [&](int s) {
        uint32_t Ah = sb + (uint32_t)s * STAGE_BYTES;
        uint32_t Al = Ah + TEN_BYTES;
        uint32_t Bh = Ah + 2 * TEN_BYTES;
        uint32_t Bl = Ah + 3 * TEN_BYTES;
#pragma unroll
        for (int ks = 0; ks < 4; ++ks) {
            uint32_t aH[2][4], aL[2][4], bH[4][4], bL[4][4];
#pragma unroll
            for (int t = 0; t < 2; ++t) {
                uint32_t ra = (uint32_t)((wm * 32 + t * 16 + (lane & 15)) * ROWB +
                                         ks * 32 + (lane >> 4) * 16);
                ldsm4(aH[t], Ah + ra);
                ldsm4(aL[t], Al + ra);
            }
#pragma unroll
            for (int t = 0; t < 4; ++t) {
                uint32_t rb = (uint32_t)((wn * 64 + t * 16 + (lane & 15)) * ROWB +
                                         ks * 32 + (lane >> 4) * 16);
                ldsm4(bH[t], Bh + rb);
                ldsm4(bL[t], Bl + rb);
            }
#pragma unroll
            for (int mi = 0; mi < 2; ++mi)
#pragma unroll
                for (int nt = 0; nt < 4; ++nt) {
                    // pass 0: Ahi x Bhi
                    mma16816(acc[mi][2 * nt], aH[mi], bH[nt][0], bH[nt][2]);
                    mma16816(acc[mi][2 * nt + 1], aH[mi], bH[nt][1], bH[nt][3]);
                    // pass 1: Ahi x Blo
                    mma16816(acc[mi][2 * nt], aH[mi], bL[nt][0], bL[nt][2]);
                    mma16816(acc[mi][2 * nt + 1], aH[mi], bL[nt][1], bL[nt][3]);
                    // pass 2: Alo x Bhi
                    mma16816(acc[mi][2 * nt], aL[mi], bH[nt][0], bH[nt][2]);
                    mma16816(acc[mi][2 * nt + 1], aL[mi], bH[nt][1], bH[nt][3]);
                }
        }
    };

    load_chunk(0, 0);
    CP_COMMIT();
#pragma unroll 1
    for (int c = 0; c < 144; ++c) {
        int s = c & 1;
        if (c + 1 < 144) {
            load_chunk(c + 1, s ^ 1);
            CP_COMMIT();
            CP_WAIT1();
        } else {
            CP_WAIT0();
        }
        __syncthreads();
        compute(s);
        __syncthreads();
    }

    // epilogue: bias + relu -> g_h[b][co][p]
#pragma unroll
    for (int mi = 0; mi < 2; ++mi) {
        int r0 = wm * 32 + mi * 16 + (lane >> 2);
#pragma unroll
        for (int nt = 0; nt < 8; ++nt) {
            int co = co0 + wn * 64 + nt * 8 + (lane & 3) * 2;
            float bv0 = b1[co], bv1 = b1[co + 1];
            float* q0 = &g_h[((size_t)(bb * CM + co)) * HW];
            float* q1 = &g_h[((size_t)(bb * CM + co + 1)) * HW];
            q0[p0 + r0] = fmaxf(acc[mi][nt][0] + bv0, 0.f);
            q1[p0 + r0] = fmaxf(acc[mi][nt][1] + bv1, 0.f);
            q0[p0 + r0 + 8] = fmaxf(acc[mi][nt][2] + bv0, 0.f);
            q1[p0 + r0 + 8] = fmaxf(acc[mi][nt][3] + bv1, 0.f);
        }
    }
}

// 1x1 conv over 512 channels + softplus; writes heatmap to scratch and d_out+3.
__global__ void heat_kernel(const float* __restrict__ w2,
                            const float* __restrict__ b2, float* __restrict__ out) {
    int b = blockIdx.x;
    int p = blockIdx.y * 256 + threadIdx.x;
    float acc = b2[0];
    const float* hp = g_h + (size_t)b * CM * HW + p;
#pragma unroll 4
    for (int c = 0; c < CM; ++c) acc += hp[(size_t)c * HW] * w2[c];
    float sp = fmaxf(acc, 0.f) + log1pf(expf(-fabsf(acc)));
    g_heat[b * HW + p] = sp;
    out[3 + b * HW + p] = sp;
}

// per-batch: normalize to prob, add JAX (partitionable threefry) Gumbel -> score
__global__ void score_kernel() {
    __shared__ float sh[33];
    int b = blockIdx.x;
    float s = 0.f;
    for (int p = threadIdx.x; p < HW; p += 256) s += g_heat[b * HW + p];
    float S = block_sum_256(s, sh);
    for (int p = threadIdx.x; p < HW; p += 256) {
        unsigned gi = (unsigned)(b * HW + p);
        unsigned o0, o1;
        threefry2x32(0u, 42u, 0u, gi, o0, o1);
        unsigned bits = o0 ^ o1;
        float f = __uint_as_float((bits >> 9) | 0x3f800000u) - 1.0f;
        float u = fmaxf(1e-8f, f * (1.0f - 1e-8f) + 1e-8f);
        float gum = -logf(-logf(u));
        g_score[gi] = logf(g_heat[gi] / (S + 1e-6f) + 1e-12f) + gum;
    }
}

// top-256 per batch via in-smem bitonic sort
__global__ void topk_kernel() {
    __shared__ float key[HW];
    __shared__ int val[HW];
    int b = blockIdx.x;
    for (int i = threadIdx.x; i < HW; i += blockDim.x) {
        key[i] = -g_score[b * HW + i];
        val[i] = i;
    }
    for (int k = 2; k <= HW; k <<= 1)
        for (int j = k >> 1; j > 0; j >>= 1) {
            __syncthreads();
            for (int i = threadIdx.x; i < HW; i += blockDim.x) {
                int p = i ^ j;
                if (p > i) {
                    bool up = ((i & k) == 0);
                    float ki = key[i], kp = key[p];
                    if ((ki > kp) == up) {
                        key[i] = kp;
                        key[p] = ki;
                        int t = val[i];
                        val[i] = val[p];
                        val[p] = t;
                    }
                }
            }
        }
    __syncthreads();
    for (int i = threadIdx.x; i < NA; i += blockDim.x) g_idx[b * NA + i] = val[i];
}

// bilinear sample == 0.25 * sum of 4 pixels with zero pad
__global__ void gather_kernel(const float* __restrict__ T,
                              const float* __restrict__ Sf) {
    int blk = blockIdx.x;
    int b = blk >> 8, n = blk & 255;
    int idx = g_idx[b * NA + n];
    int r = idx >> 6, c = idx & 63;
    bool rv = r > 0, cv = c > 0;
    int o11 = r * WW + c, o10 = o11 - 1, o01 = o11 - WW, o00 = o01 - 1;
    for (int ch = threadIdx.x; ch < CT; ch += blockDim.x) {
        const float* base = T + (size_t)(b * CT + ch) * HW;
        float s = base[o11];
        if (cv) s += base[o10];
        if (rv) {
            s += base[o01];
            if (cv) s += base[o00];
        }
        g_sampT[(size_t)(b * NA + n) * CT + ch] = 0.25f * s;
    }
    for (int ch = threadIdx.x; ch < CS; ch += blockDim.x) {
        const float* base = Sf + (size_t)(b * CS + ch) * HW;
        float s = base[o11];
        if (cv) s += base[o10];
        if (rv) {
            s += base[o01];
            if (cv) s += base[o00];
        }
        g_sampS[(size_t)(b * NA + n) * CS + ch] = 0.25f * s;
    }
    if (threadIdx.x == 0) {
        const float* base = g_heat + b * HW;
        float s = base[o11];
        if (cv) s += base[o10];
        if (rv) {
            s += base[o01];
            if (cv) s += base[o00];
        }
        g_sal[b * NA + n] = 0.25f * s;
    }
}

// [rows,C]@[C,256] + bias -> LayerNorm -> l2norm. 8 rows per block, thread = p.
template <int C>
__global__ void proj_kernel(const float* __restrict__ wmat,
                            const float* __restrict__ bias,
                            const float* __restrict__ gamma,
                            const float* __restrict__ beta) {
    __shared__ float sRow[8 * C];
    __shared__ float sh[33];
    const float* samp = (C == CT) ? g_sampT : g_sampS;
    float* outp = (C == CT) ? g_ft : g_fs;
    int a0 = blockIdx.x * 8;
    int p = threadIdx.x;
    for (int i = threadIdx.x; i < 8 * C; i += 256) sRow[i] = samp[(size_t)a0 * C + i];
    __syncthreads();
    float acc[8];
#pragma unroll
    for (int i = 0; i < 8; ++i) acc[i] = 0.f;
    for (int c = 0; c < C; ++c) {
        float w = wmat[(size_t)c * NP + p];
#pragma unroll
        for (int i = 0; i < 8; ++i) acc[i] += sRow[i * C + c] * w;
    }
    float bi = bias[p], ga = gamma[p], be = beta[p];
#pragma unroll 1
    for (int i = 0; i < 8; ++i) {
        float x = acc[i] + bi;
        float mu = block_sum_256(x, sh) * (1.0f / NP);
        float d = x - mu;
        float var = block_sum_256(d * d, sh) * (1.0f / NP);
        float y = d * rsqrtf(var + 1e-5f) * ga + be;
        float nrm = sqrtf(block_sum_256(y * y, sh));
        y = y / fmaxf(nrm, 1e-12f);
        outp[(size_t)(a0 + i) * NP + p] = y;
    }
}

__global__ void gafd_kernel() {
    __shared__ float sh[33];
    float s = 0.f;
    const int total = NB * NA * NP;
    for (int i = blockIdx.x * blockDim.x + threadIdx.x; i < total;
         i += gridDim.x * blockDim.x) {
        float d = g_fs[i] - g_ft[i];
        s += d * d;
    }
    float bs = block_sum_256(s, sh);
    if (threadIdx.x == 0) atomicAdd(&g_gafd, bs);
}

__global__ void bd_kernel() {
    __shared__ float sh[33];
    int b = blockIdx.x;
    float s = g_sal[b * NA + threadIdx.x];
    float mx = block_max_256(s, sh);
    int bd = (s > 0.6f * mx) ? 1 : 0;
    g_bd[b * NA + threadIdx.x] = bd;
    float cnt = block_sum_256((float)bd, sh);
    if (threadIdx.x == 0) g_cnt[b] = (int)(cnt + 0.5f);
}

__global__ void abcd_kernel() {
    __shared__ float fsn[NP];
    __shared__ float sh[33];
    int blk = blockIdx.x;
    int b = blk >> 8, n = blk & 255;
    if (!g_bd[b * NA + n]) return;
    int t = threadIdx.x;
    float fv = g_fs[(size_t)(b * NA + n) * NP + t];
    float ftv = g_ft[(size_t)(b * NA + n) * NP + t];
    fsn[t] = fv;
    __syncthreads();
    float pos = block_sum_256(fv * ftv, sh) * 10.0f;  // /TAU
    const float4* fm = (const float4*)(g_fs + (size_t)(b * NA + t) * NP);
    float dm = 0.f;
#pragma unroll 4
    for (int q = 0; q < NP / 4; ++q) {
        float4 v = fm[q];
        dm += fsn[4 * q] * v.x + fsn[4 * q + 1] * v.y + fsn[4 * q + 2] * v.z +
              fsn[4 * q + 3] * v.w;
    }
    float val = g_bd[b * NA + t] ? -1e30f : dm * 10.0f;
    float mx = fmaxf(pos, block_max_256(val, sh));
    float e = (val < -1e29f) ? 0.f : expf(val - mx);
    float ssum = block_sum_256(e, sh) + expf(pos - mx);
    if (t == 0) atomicAdd(&g_abcd_b[b], mx + logf(ssum) - pos);
}

__global__ void final_kernel(float* __restrict__ out) {
    int t = threadIdx.x;
    float per = 0.f, valid = 0.f;
    if (t < NB) {
        int c = g_cnt[t];
        per = g_abcd_b[t] / fmaxf((float)c, 1.0f);
        valid = (c > 0 && c < NA) ? 1.0f : 0.0f;
    }
    float pv = per * valid;
#pragma unroll
    for (int o = 16; o; o >>= 1) {
        pv += __shfl_down_sync(0xffffffffu, pv, o);
        valid += __shfl_down_sync(0xffffffffu, valid, o);
    }
    if (t == 0) {
        float gafd = g_gafd * (1.0f / (NB * NA * NP));
        float abcd = (valid > 0.f) ? pv / valid : 0.f;
        out[0] = gafd + 0.5f * abcd;
        out[1] = gafd;
        out[2] = abcd;
    }
}

// ---------------- host launch ----------------
extern "C" void kernel_launch(void* const* d_in, const int* in_sizes, int n_in,
                              void* d_out, int out_size) {
    const float* T = (const float*)d_in[0];
    const float* Sf = (const float*)d_in[1];
    const float* w1 = (const float*)d_in[2];
    const float* b1 = (const float*)d_in[3];
    const float* w2 = (const float*)d_in[4];
    const float* b2 = (const float*)d_in[5];
    const float* tw = (const float*)d_in[6];
    const float* tb = (const float*)d_in[7];
    const float* tg = (const float*)d_in[8];
    const float* tbe = (const float*)d_in[9];
    const float* sw = (const float*)d_in[10];
    const float* sb = (const float*)d_in[11];
    const float* sg = (const float*)d_in[12];
    const float* sbe = (const float*)d_in[13];
    float* out = (float*)d_out;

    const int DSMEM = 2 * STAGE_BYTES;  // 147456
    static int s_attr_done = 0;
    if (!s_attr_done) {
        cudaFuncSetAttribute(convmma_kernel,
                             cudaFuncAttributeMaxDynamicSharedMemorySize, DSMEM);
        s_attr_done = 1;
    }

    reset_kernel<<<1, 32>>>();
    tprep_kernel<<<dim3(128, 32, 16), dim3(32, 8)>>>(T);
    wprep_kernel<<<(9 * CM * CT + 255) / 256, 256>>>(w1);
    convmma_kernel<<<dim3(4, 32, 16), 256, DSMEM>>>(b1);
    heat_kernel<<<dim3(16, 16), 256>>>(w2, b2, out);
    score_kernel<<<16, 256>>>();
    topk_kernel<<<16, 512>>>();
    gather_kernel<<<NB * NA, 256>>>(T, Sf);
    proj_kernel<CT><<<512, 256>>>(tw, tb, tg, tbe);
    proj_kernel<CS><<<512, 256>>>(sw, sb, sg, sbe);
    gafd_kernel<<<256, 256>>>();
    bd_kernel<<<NB, 256>>>();
    abcd_kernel<<<NB * NA, 256>>>();
    final_kernel<<<1, 32>>>(out);
}

// round 8
// speedup vs baseline: 2.6572x; 1.0574x over previous
#include <cuda_runtime.h>
#include <cuda_bf16.h>
#include <math.h>
#include <stdint.h>

#define NB 16
#define CT 1024
#define CS 512
#define CM 512
#define HH 64
#define WW 64
#define HW 4096
#define NP 256
#define NA 256

// ---------------- scratch (device globals; no allocation) ----------------
__device__ float g_h[NB * CM * HW];   // conv1 output, relu applied (134 MB)
__device__ float g_heat[NB * HW];
__device__ float g_score[NB * HW];
__device__ int   g_idx[NB * NA];
__device__ float g_sampT[NB * NA * CT];
__device__ float g_sampS[NB * NA * CS];
__device__ float g_sal[NB * NA];
__device__ float g_ft[NB * NA * NP];
__device__ float g_fs[NB * NA * NP];
__device__ int   g_bd[NB * NA];
__device__ int   g_cnt[NB];
__device__ float g_gafd;
__device__ float g_abcd_b[NB];

// bf16 hi/lo split tensors for tensor-core conv
__device__ __align__(16) __nv_bfloat16 g_Thi[NB * HW * CT];      // [b][p][ci]
__device__ __align__(16) __nv_bfloat16 g_Tlo[NB * HW * CT];
__device__ __align__(16) __nv_bfloat16 g_Whi[9 * CM * CT];       // [tap][co][ci]
__device__ __align__(16) __nv_bfloat16 g_Wlo[9 * CM * CT];

// ---------------- sm_80-class PTX helpers (compile on compute_103) --------
__device__ __forceinline__ uint32_t smem_to_u32(const void* smem_ptr) {
    uint32_t addr;
    asm("{ .reg .u64 tmp; cvta.to.shared.u64 tmp, %1; cvt.u32.u64 %0, tmp; }"
        : "=r"(addr) : "l"(smem_ptr));
    return addr;
}
__device__ __forceinline__ void cp16(uint32_t dst, const void* src, bool ok) {
    int sz = ok ? 16 : 0;
    asm volatile("cp.async.cg.shared.global [%0], [%1], 16, %2;"
                 :: "r"(dst), "l"(src), "r"(sz) : "memory");
}
#define CP_COMMIT() asm volatile("cp.async.commit_group;" ::: "memory")
#define CP_WAIT1()  asm volatile("cp.async.wait_group 1;" ::: "memory")
#define CP_WAIT0()  asm volatile("cp.async.wait_group 0;" ::: "memory")

__device__ __forceinline__ void ldsm4(uint32_t* r, uint32_t addr) {
    asm volatile("ldmatrix.sync.aligned.m8n8.x4.shared.b16 {%0,%1,%2,%3}, [%4];"
                 : "=r"(r[0]), "=r"(r[1]), "=r"(r[2]), "=r"(r[3]) : "r"(addr));
}
__device__ __forceinline__ void mma16816(float* c, const uint32_t* a,
                                         uint32_t b0, uint32_t b1) {
    asm volatile(
        "mma.sync.aligned.m16n8k16.row.col.f32.bf16.bf16.f32 "
        "{%0,%1,%2,%3}, {%4,%5,%6,%7}, {%8,%9}, {%0,%1,%2,%3};"
        : "+f"(c[0]), "+f"(c[1]), "+f"(c[2]), "+f"(c[3])
        : "r"(a[0]), "r"(a[1]), "r"(a[2]), "r"(a[3]), "r"(b0), "r"(b1));
}

// ---------------- generic helpers ----------------
__device__ __forceinline__ float block_sum_256(float v, float* sh) {
#pragma unroll
    for (int o = 16; o; o >>= 1) v += __shfl_down_sync(0xffffffffu, v, o);
    __syncthreads();
    if ((threadIdx.x & 31) == 0) sh[threadIdx.x >> 5] = v;
    __syncthreads();
    if (threadIdx.x == 0) {
        float t = 0.f;
        for (int i = 0; i < 8; ++i) t += sh[i];
        sh[32] = t;
    }
    __syncthreads();
    return sh[32];
}

__device__ __forceinline__ float block_max_256(float v, float* sh) {
#pragma unroll
    for (int o = 16; o; o >>= 1) v = fmaxf(v, __shfl_down_sync(0xffffffffu, v, o));
    __syncthreads();
    if ((threadIdx.x & 31) == 0) sh[threadIdx.x >> 5] = v;
    __syncthreads();
    if (threadIdx.x == 0) {
        float t = sh[0];
        for (int i = 1; i < 8; ++i) t = fmaxf(t, sh[i]);
        sh[32] = t;
    }
    __syncthreads();
    return sh[32];
}

__device__ __forceinline__ void threefry2x32(unsigned k0, unsigned k1,
                                             unsigned x0, unsigned x1,
                                             unsigned& o0, unsigned& o1) {
    unsigned ks[3] = {k0, k1, k0 ^ k1 ^ 0x1BD11BDAu};
    x0 += ks[0];
    x1 += ks[1];
    const int R[5][4] = {{13, 15, 26, 6}, {17, 29, 16, 24}, {13, 15, 26, 6},
                         {17, 29, 16, 24}, {13, 15, 26, 6}};
#pragma unroll
    for (int g = 0; g < 5; ++g) {
#pragma unroll
        for (int q = 0; q < 4; ++q) {
            x0 += x1;
            int rr = R[g][q];
            x1 = (x1 << rr) | (x1 >> (32 - rr));
            x1 ^= x0;
        }
        x0 += ks[(g + 1) % 3];
        x1 += ks[(g + 2) % 3] + (unsigned)(g + 1);
    }
    o0 = x0;
    o1 = x1;
}

// ---------------- kernels ----------------
__global__ void reset_kernel() {
    int t = threadIdx.x;
    if (t == 0) g_gafd = 0.f;
    if (t < NB) g_abcd_b[t] = 0.f;
}

// transpose + bf16 split of teacher feat: T[b][ci][p] -> Thi/Tlo[b][p][ci]
__global__ void tprep_kernel(const float* __restrict__ T) {
    __shared__ float tile[32][33];
    int b = blockIdx.z, p0 = blockIdx.x * 32, c0 = blockIdx.y * 32;
    int tx = threadIdx.x, ty = threadIdx.y;
    for (int i = ty; i < 32; i += 8)
        tile[i][tx] = T[((size_t)(b * CT + c0 + i)) * HW + p0 + tx];
    __syncthreads();
    for (int i = ty; i < 32; i += 8) {
        float v = tile[tx][i];
        __nv_bfloat16 h = __float2bfloat16(v);
        float hf = __bfloat162float(h);
        size_t o = ((size_t)b * HW + p0 + i) * CT + c0 + tx;
        g_Thi[o] = h;
        g_Tlo[o] = __float2bfloat16(v - hf);
    }
}

// weights split: W1[co][ci][tap] -> Whi/Wlo[tap][co][ci]
__global__ void wprep_kernel(const float* __restrict__ W1) {
    int idx = blockIdx.x * blockDim.x + threadIdx.x;
    if (idx >= 9 * CM * CT) return;
    int ci = idx & (CT - 1);
    int rest = idx >> 10;
    int co = rest & (CM - 1);
    int tap = rest >> 9;
    float w = W1[((size_t)co * CT + ci) * 9 + tap];
    __nv_bfloat16 h = __float2bfloat16(w);
    float hf = __bfloat162float(h);
    g_Whi[idx] = h;
    g_Wlo[idx] = __float2bfloat16(w - hf);
}

// conv1 via mma.sync bf16x3 implicit GEMM.
// CTA: 512 threads, 128 pixels x 256 co. K loop: 9 taps x 16 chunks of 64 ci.
#define ROWB 144                      // bytes per smem row (64 bf16 + 8 pad)
#define A_BYTES (128 * ROWB)          // 18432
#define B_BYTES (256 * ROWB)          // 36864
#define STAGE_BYTES (2 * A_BYTES + 2 * B_BYTES)  // 110592
__global__ __launch_bounds__(512, 1)
void convmma_kernel(const float* __restrict__ b1) {
    extern __shared__ char dsm[];
    uint32_t sb = smem_to_u32(dsm);
    int tid = threadIdx.x, lane = tid & 31, wid = tid >> 5;
    int co0 = blockIdx.x * 256;
    int pixtile = blockIdx.y;
    int bb = blockIdx.z;
    int y0 = pixtile * 2, p0 = pixtile * 128;
    int wm = wid & 3, wn = wid >> 2;   // wm: 4 M-groups of 32 px; wn: 4 N-groups of 64 co

    float acc[2][8][4];
#pragma unroll
    for (int i = 0; i < 2; ++i)
#pragma unroll
        for (int j = 0; j < 8; ++j)
#pragma unroll
            for (int k = 0; k < 4; ++k) acc[i][j][k] = 0.f;

    auto load_chunk = [&](int c, int s) {
        int tap = c >> 4, kc = c & 15;
        int dy = tap / 3 - 1, dx = tap % 3 - 1;
        int ci0 = kc * 64;
        uint32_t base = sb + (uint32_t)s * STAGE_BYTES;
        // A: 128 pixel rows x 64 ci, shifted + zero-masked (hi @0, lo @A_BYTES)
#pragma unroll
        for (int i = 0; i < 2; ++i) {
            int u = i * 512 + tid;
            int r = u >> 3, seg = u & 7;
            int ys = y0 + (r >> 6) + dy;
            int xs = (r & 63) + dx;
            bool ok = ((unsigned)ys < 64u) && ((unsigned)xs < 64u);
            int ysc = ok ? ys : 0, xsc = ok ? xs : 0;
            size_t g = ((size_t)(bb * HW + ysc * 64 + xsc)) * CT + ci0 + seg * 8;
            uint32_t off = (uint32_t)(r * ROWB + seg * 16);
            cp16(base + off, g_Thi + g, ok);
            cp16(base + A_BYTES + off, g_Tlo + g, ok);
        }
        // B: 256 co rows x 64 ci (hi @2*A_BYTES, lo @2*A_BYTES+B_BYTES)
#pragma unroll
        for (int i = 0; i < 4; ++i) {
            int u = i * 512 + tid;
            int r = u >> 3, seg = u & 7;
            size_t g = ((size_t)(tap * CM + co0 + r)) * CT + ci0 + seg * 8;
            uint32_t off = (uint32_t)(r * ROWB + seg * 16);
            cp16(base + 2 * A_BYTES + off, g_Whi + g, true);
            cp16(base + 2 * A_BYTES + B_BYTES + off, g_Wlo + g, true);
        }
    };

    auto compute = [&](int s) {
        uint32_t Ah = sb + (uint32_t)s * STAGE_BYTES;
        uint32_t Al = Ah + A_BYTES;
        uint32_t Bh = Ah + 2 * A_BYTES;
        uint32_t Bl = Bh + B_BYTES;
#pragma unroll
        for (int ks = 0; ks < 4; ++ks) {
            uint32_t aH[2][4], aL[2][4];
#pragma unroll
            for (int t = 0; t < 2; ++t) {
                uint32_t ra = (uint32_t)((wm * 32 + t * 16 + (lane & 15)) * ROWB +
                                         ks * 32 + (lane >> 4) * 16);
                ldsm4(aH[t], Ah + ra);
                ldsm4(aL[t], Al + ra);
            }
#pragma unroll
            for (int nt = 0; nt < 4; ++nt) {
                uint32_t rb = (uint32_t)((wn * 64 + nt * 16 + (lane & 15)) * ROWB +
                                         ks * 32 + (lane >> 4) * 16);
                uint32_t bH[4], bL[4];
                ldsm4(bH, Bh + rb);
                ldsm4(bL, Bl + rb);
#pragma unroll
                for (int mi = 0; mi < 2; ++mi) {
                    // pass 0: Ahi x Bhi
                    mma16816(acc[mi][2 * nt], aH[mi], bH[0], bH[2]);
                    mma16816(acc[mi][2 * nt + 1], aH[mi], bH[1], bH[3]);
                    // pass 2: Alo x Bhi (bH still live)
                    mma16816(acc[mi][2 * nt], aL[mi], bH[0], bH[2]);
                    mma16816(acc[mi][2 * nt + 1], aL[mi], bH[1], bH[3]);
                    // pass 1: Ahi x Blo
                    mma16816(acc[mi][2 * nt], aH[mi], bL[0], bL[2]);
                    mma16816(acc[mi][2 * nt + 1], aH[mi], bL[1], bL[3]);
                }
            }
        }
    };

    load_chunk(0, 0);
    CP_COMMIT();
#pragma unroll 1
    for (int c = 0; c < 144; ++c) {
        int s = c & 1;
        if (c + 1 < 144) {
            load_chunk(c + 1, s ^ 1);
            CP_COMMIT();
            CP_WAIT1();
        } else {
            CP_WAIT0();
        }
        __syncthreads();
        compute(s);
        __syncthreads();
    }

    // epilogue: bias + relu -> g_h[b][co][p]
#pragma unroll
    for (int mi = 0; mi < 2; ++mi) {
        int r0 = wm * 32 + mi * 16 + (lane >> 2);
#pragma unroll
        for (int nt = 0; nt < 8; ++nt) {
            int co = co0 + wn * 64 + nt * 8 + (lane & 3) * 2;
            float bv0 = b1[co], bv1 = b1[co + 1];
            float* q0 = &g_h[((size_t)(bb * CM + co)) * HW];
            float* q1 = &g_h[((size_t)(bb * CM + co + 1)) * HW];
            q0[p0 + r0] = fmaxf(acc[mi][nt][0] + bv0, 0.f);
            q1[p0 + r0] = fmaxf(acc[mi][nt][1] + bv1, 0.f);
            q0[p0 + r0 + 8] = fmaxf(acc[mi][nt][2] + bv0, 0.f);
            q1[p0 + r0 + 8] = fmaxf(acc[mi][nt][3] + bv1, 0.f);
        }
    }
}

// 1x1 conv over 512 channels + softplus; writes heatmap to scratch and d_out+3.
__global__ void heat_kernel(const float* __restrict__ w2,
                            const float* __restrict__ b2, float* __restrict__ out) {
    int b = blockIdx.x;
    int p = blockIdx.y * 256 + threadIdx.x;
    float acc = b2[0];
    const float* hp = g_h + (size_t)b * CM * HW + p;
#pragma unroll 4
    for (int c = 0; c < CM; ++c) acc += hp[(size_t)c * HW] * w2[c];
    float sp = fmaxf(acc, 0.f) + log1pf(expf(-fabsf(acc)));
    g_heat[b * HW + p] = sp;
    out[3 + b * HW + p] = sp;
}

// per-batch: normalize to prob, add JAX (partitionable threefry) Gumbel -> score
__global__ void score_kernel() {
    __shared__ float sh[33];
    int b = blockIdx.x;
    float s = 0.f;
    for (int p = threadIdx.x; p < HW; p += 256) s += g_heat[b * HW + p];
    float S = block_sum_256(s, sh);
    for (int p = threadIdx.x; p < HW; p += 256) {
        unsigned gi = (unsigned)(b * HW + p);
        unsigned o0, o1;
        threefry2x32(0u, 42u, 0u, gi, o0, o1);
        unsigned bits = o0 ^ o1;
        float f = __uint_as_float((bits >> 9) | 0x3f800000u) - 1.0f;
        float u = fmaxf(1e-8f, f * (1.0f - 1e-8f) + 1e-8f);
        float gum = -logf(-logf(u));
        g_score[gi] = logf(g_heat[gi] / (S + 1e-6f) + 1e-12f) + gum;
    }
}

// top-256 per batch via in-smem bitonic sort
__global__ void topk_kernel() {
    __shared__ float key[HW];
    __shared__ int val[HW];
    int b = blockIdx.x;
    for (int i = threadIdx.x; i < HW; i += blockDim.x) {
        key[i] = -g_score[b * HW + i];
        val[i] = i;
    }
    for (int k = 2; k <= HW; k <<= 1)
        for (int j = k >> 1; j > 0; j >>= 1) {
            __syncthreads();
            for (int i = threadIdx.x; i < HW; i += blockDim.x) {
                int p = i ^ j;
                if (p > i) {
                    bool up = ((i & k) == 0);
                    float ki = key[i], kp = key[p];
                    if ((ki > kp) == up) {
                        key[i] = kp;
                        key[p] = ki;
                        int t = val[i];
                        val[i] = val[p];
                        val[p] = t;
                    }
                }
            }
        }
    __syncthreads();
    for (int i = threadIdx.x; i < NA; i += blockDim.x) g_idx[b * NA + i] = val[i];
}

// bilinear sample == 0.25 * sum of 4 pixels with zero pad
__global__ void gather_kernel(const float* __restrict__ T,
                              const float* __restrict__ Sf) {
    int blk = blockIdx.x;
    int b = blk >> 8, n = blk & 255;
    int idx = g_idx[b * NA + n];
    int r = idx >> 6, c = idx & 63;
    bool rv = r > 0, cv = c > 0;
    int o11 = r * WW + c, o10 = o11 - 1, o01 = o11 - WW, o00 = o01 - 1;
    for (int ch = threadIdx.x; ch < CT; ch += blockDim.x) {
        const float* base = T + (size_t)(b * CT + ch) * HW;
        float s = base[o11];
        if (cv) s += base[o10];
        if (rv) {
            s += base[o01];
            if (cv) s += base[o00];
        }
        g_sampT[(size_t)(b * NA + n) * CT + ch] = 0.25f * s;
    }
    for (int ch = threadIdx.x; ch < CS; ch += blockDim.x) {
        const float* base = Sf + (size_t)(b * CS + ch) * HW;
        float s = base[o11];
        if (cv) s += base[o10];
        if (rv) {
            s += base[o01];
            if (cv) s += base[o00];
        }
        g_sampS[(size_t)(b * NA + n) * CS + ch] = 0.25f * s;
    }
    if (threadIdx.x == 0) {
        const float* base = g_heat + b * HW;
        float s = base[o11];
        if (cv) s += base[o10];
        if (rv) {
            s += base[o01];
            if (cv) s += base[o00];
        }
        g_sal[b * NA + n] = 0.25f * s;
    }
}

// [rows,C]@[C,256] + bias -> LayerNorm -> l2norm. 8 rows per block, thread = p.
template <int C>
__global__ void proj_kernel(const float* __restrict__ wmat,
                            const float* __restrict__ bias,
                            const float* __restrict__ gamma,
                            const float* __restrict__ beta) {
    __shared__ float sRow[8 * C];
    __shared__ float sh[33];
    const float* samp = (C == CT) ? g_sampT : g_sampS;
    float* outp = (C == CT) ? g_ft : g_fs;
    int a0 = blockIdx.x * 8;
    int p = threadIdx.x;
    for (int i = threadIdx.x; i < 8 * C; i += 256) sRow[i] = samp[(size_t)a0 * C + i];
    __syncthreads();
    float acc[8];
#pragma unroll
    for (int i = 0; i < 8; ++i) acc[i] = 0.f;
    for (int c = 0; c < C; ++c) {
        float w = wmat[(size_t)c * NP + p];
#pragma unroll
        for (int i = 0; i < 8; ++i) acc[i] += sRow[i * C + c] * w;
    }
    float bi = bias[p], ga = gamma[p], be = beta[p];
#pragma unroll 1
    for (int i = 0; i < 8; ++i) {
        float x = acc[i] + bi;
        float mu = block_sum_256(x, sh) * (1.0f / NP);
        float d = x - mu;
        float var = block_sum_256(d * d, sh) * (1.0f / NP);
        float y = d * rsqrtf(var + 1e-5f) * ga + be;
        float nrm = sqrtf(block_sum_256(y * y, sh));
        y = y / fmaxf(nrm, 1e-12f);
        outp[(size_t)(a0 + i) * NP + p] = y;
    }
}

__global__ void gafd_kernel() {
    __shared__ float sh[33];
    float s = 0.f;
    const int total = NB * NA * NP;
    for (int i = blockIdx.x * blockDim.x + threadIdx.x; i < total;
         i += gridDim.x * blockDim.x) {
        float d = g_fs[i] - g_ft[i];
        s += d * d;
    }
    float bs = block_sum_256(s, sh);
    if (threadIdx.x == 0) atomicAdd(&g_gafd, bs);
}

__global__ void bd_kernel() {
    __shared__ float sh[33];
    int b = blockIdx.x;
    float s = g_sal[b * NA + threadIdx.x];
    float mx = block_max_256(s, sh);
    int bd = (s > 0.6f * mx) ? 1 : 0;
    g_bd[b * NA + threadIdx.x] = bd;
    float cnt = block_sum_256((float)bd, sh);
    if (threadIdx.x == 0) g_cnt[b] = (int)(cnt + 0.5f);
}

__global__ void abcd_kernel() {
    __shared__ float fsn[NP];
    __shared__ float sh[33];
    int blk = blockIdx.x;
    int b = blk >> 8, n = blk & 255;
    if (!g_bd[b * NA + n]) return;
    int t = threadIdx.x;
    float fv = g_fs[(size_t)(b * NA + n) * NP + t];
    float ftv = g_ft[(size_t)(b * NA + n) * NP + t];
    fsn[t] = fv;
    __syncthreads();
    float pos = block_sum_256(fv * ftv, sh) * 10.0f;  // /TAU
    const float4* fm = (const float4*)(g_fs + (size_t)(b * NA + t) * NP);
    float dm = 0.f;
#pragma unroll 4
    for (int q = 0; q < NP / 4; ++q) {
        float4 v = fm[q];
        dm += fsn[4 * q] * v.x + fsn[4 * q + 1] * v.y + fsn[4 * q + 2] * v.z +
              fsn[4 * q + 3] * v.w;
    }
    float val = g_bd[b * NA + t] ? -1e30f : dm * 10.0f;
    float mx = fmaxf(pos, block_max_256(val, sh));
    float e = (val < -1e29f) ? 0.f : expf(val - mx);
    float ssum = block_sum_256(e, sh) + expf(pos - mx);
    if (t == 0) atomicAdd(&g_abcd_b[b], mx + logf(ssum) - pos);
}

__global__ void final_kernel(float* __restrict__ out) {
    int t = threadIdx.x;
    float per = 0.f, valid = 0.f;
    if (t < NB) {
        int c = g_cnt[t];
        per = g_abcd_b[t] / fmaxf((float)c, 1.0f);
        valid = (c > 0 && c < NA) ? 1.0f : 0.0f;
    }
    float pv = per * valid;
#pragma unroll
    for (int o = 16; o; o >>= 1) {
        pv += __shfl_down_sync(0xffffffffu, pv, o);
        valid += __shfl_down_sync(0xffffffffu, valid, o);
    }
    if (t == 0) {
        float gafd = g_gafd * (1.0f / (NB * NA * NP));
        float abcd = (valid > 0.f) ? pv / valid : 0.f;
        out[0] = gafd + 0.5f * abcd;
        out[1] = gafd;
        out[2] = abcd;
    }
}

// ---------------- host launch ----------------
extern "C" void kernel_launch(void* const* d_in, const int* in_sizes, int n_in,
                              void* d_out, int out_size) {
    const float* T = (const float*)d_in[0];
    const float* Sf = (const float*)d_in[1];
    const float* w1 = (const float*)d_in[2];
    const float* b1 = (const float*)d_in[3];
    const float* w2 = (const float*)d_in[4];
    const float* b2 = (const float*)d_in[5];
    const float* tw = (const float*)d_in[6];
    const float* tb = (const float*)d_in[7];
    const float* tg = (const float*)d_in[8];
    const float* tbe = (const float*)d_in[9];
    const float* sw = (const float*)d_in[10];
    const float* sb = (const float*)d_in[11];
    const float* sg = (const float*)d_in[12];
    const float* sbe = (const float*)d_in[13];
    float* out = (float*)d_out;

    const int DSMEM = 2 * STAGE_BYTES;  // 221184
    static int s_attr_done = 0;
    if (!s_attr_done) {
        cudaFuncSetAttribute(convmma_kernel,
                             cudaFuncAttributeMaxDynamicSharedMemorySize, DSMEM);
        s_attr_done = 1;
    }

    reset_kernel<<<1, 32>>>();
    tprep_kernel<<<dim3(128, 32, 16), dim3(32, 8)>>>(T);
    wprep_kernel<<<(9 * CM * CT + 255) / 256, 256>>>(w1);
    convmma_kernel<<<dim3(2, 32, 16), 512, DSMEM>>>(b1);
    heat_kernel<<<dim3(16, 16), 256>>>(w2, b2, out);
    score_kernel<<<16, 256>>>();
    topk_kernel<<<16, 512>>>();
    gather_kernel<<<NB * NA, 256>>>(T, Sf);
    proj_kernel<CT><<<512, 256>>>(tw, tb, tg, tbe);
    proj_kernel<CS><<<512, 256>>>(sw, sb, sg, sbe);
    gafd_kernel<<<256, 256>>>();
    bd_kernel<<<NB, 256>>>();
    abcd_kernel<<<NB * NA, 256>>>();
    final_kernel<<<1, 32>>>(out);
}

// round 9
// speedup vs baseline: 2.7993x; 1.0535x over previous
#include <cuda_runtime.h>
#include <cuda_bf16.h>
#include <math.h>
#include <stdint.h>

#define NB 16
#define CT 1024
#define CS 512
#define CM 512
#define HH 64
#define WW 64
#define HW 4096
#define NP 256
#define NA 256

// ---------------- scratch (device globals; no allocation) ----------------
__device__ float g_h[NB * CM * HW];   // conv1 output, relu applied (134 MB)
__device__ float g_heat[NB * HW];
__device__ float g_score[NB * HW];
__device__ int   g_idx[NB * NA];
__device__ float g_sampT[NB * NA * CT];
__device__ float g_sampS[NB * NA * CS];
__device__ float g_sal[NB * NA];
__device__ float g_ft[NB * NA * NP];
__device__ float g_fs[NB * NA * NP];
__device__ int   g_bd[NB * NA];
__device__ int   g_cnt[NB];
__device__ float g_gafd;
__device__ float g_abcd_b[NB];

// bf16 hi/lo split tensors for tensor-core conv
__device__ __align__(16) __nv_bfloat16 g_Thi[NB * HW * CT];      // [b][p][ci]
__device__ __align__(16) __nv_bfloat16 g_Tlo[NB * HW * CT];
__device__ __align__(16) __nv_bfloat16 g_Whi[9 * CM * CT];       // [tap][co][ci]
__device__ __align__(16) __nv_bfloat16 g_Wlo[9 * CM * CT];

// ---------------- sm_80-class PTX helpers (compile on compute_103) --------
__device__ __forceinline__ uint32_t smem_to_u32(const void* smem_ptr) {
    uint32_t addr;
    asm("{ .reg .u64 tmp; cvta.to.shared.u64 tmp, %1; cvt.u32.u64 %0, tmp; }"
        : "=r"(addr) : "l"(smem_ptr));
    return addr;
}
__device__ __forceinline__ void cp16(uint32_t dst, const void* src, bool ok) {
    int sz = ok ? 16 : 0;
    asm volatile("cp.async.cg.shared.global [%0], [%1], 16, %2;"
                 :: "r"(dst), "l"(src), "r"(sz) : "memory");
}
#define CP_COMMIT() asm volatile("cp.async.commit_group;" ::: "memory")
#define CP_WAIT0()  asm volatile("cp.async.wait_group 0;" ::: "memory")

__device__ __forceinline__ void ldsm4(uint32_t* r, uint32_t addr) {
    asm volatile("ldmatrix.sync.aligned.m8n8.x4.shared.b16 {%0,%1,%2,%3}, [%4];"
                 : "=r"(r[0]), "=r"(r[1]), "=r"(r[2]), "=r"(r[3]) : "r"(addr));
}
__device__ __forceinline__ void mma16816(float* c, const uint32_t* a,
                                         uint32_t b0, uint32_t b1) {
    asm volatile(
        "mma.sync.aligned.m16n8k16.row.col.f32.bf16.bf16.f32 "
        "{%0,%1,%2,%3}, {%4,%5,%6,%7}, {%8,%9}, {%0,%1,%2,%3};"
        : "+f"(c[0]), "+f"(c[1]), "+f"(c[2]), "+f"(c[3])
        : "r"(a[0]), "r"(a[1]), "r"(a[2]), "r"(a[3]), "r"(b0), "r"(b1));
}

// ---------------- generic helpers ----------------
__device__ __forceinline__ float block_sum_256(float v, float* sh) {
#pragma unroll
    for (int o = 16; o; o >>= 1) v += __shfl_down_sync(0xffffffffu, v, o);
    __syncthreads();
    if ((threadIdx.x & 31) == 0) sh[threadIdx.x >> 5] = v;
    __syncthreads();
    if (threadIdx.x == 0) {
        float t = 0.f;
        for (int i = 0; i < 8; ++i) t += sh[i];
        sh[32] = t;
    }
    __syncthreads();
    return sh[32];
}

__device__ __forceinline__ float block_max_256(float v, float* sh) {
#pragma unroll
    for (int o = 16; o; o >>= 1) v = fmaxf(v, __shfl_down_sync(0xffffffffu, v, o));
    __syncthreads();
    if ((threadIdx.x & 31) == 0) sh[threadIdx.x >> 5] = v;
    __syncthreads();
    if (threadIdx.x == 0) {
        float t = sh[0];
        for (int i = 1; i < 8; ++i) t = fmaxf(t, sh[i]);
        sh[32] = t;
    }
    __syncthreads();
    return sh[32];
}

__device__ __forceinline__ void threefry2x32(unsigned k0, unsigned k1,
                                             unsigned x0, unsigned x1,
                                             unsigned& o0, unsigned& o1) {
    unsigned ks[3] = {k0, k1, k0 ^ k1 ^ 0x1BD11BDAu};
    x0 += ks[0];
    x1 += ks[1];
    const int R[5][4] = {{13, 15, 26, 6}, {17, 29, 16, 24}, {13, 15, 26, 6},
                         {17, 29, 16, 24}, {13, 15, 26, 6}};
#pragma unroll
    for (int g = 0; g < 5; ++g) {
#pragma unroll
        for (int q = 0; q < 4; ++q) {
            x0 += x1;
            int rr = R[g][q];
            x1 = (x1 << rr) | (x1 >> (32 - rr));
            x1 ^= x0;
        }
        x0 += ks[(g + 1) % 3];
        x1 += ks[(g + 2) % 3] + (unsigned)(g + 1);
    }
    o0 = x0;
    o1 = x1;
}

// ---------------- kernels ----------------
__global__ void reset_kernel() {
    int t = threadIdx.x;
    if (t == 0) g_gafd = 0.f;
    if (t < NB) g_abcd_b[t] = 0.f;
}

// transpose + bf16 split of teacher feat: T[b][ci][p] -> Thi/Tlo[b][p][ci]
__global__ void tprep_kernel(const float* __restrict__ T) {
    __shared__ float tile[32][33];
    int b = blockIdx.z, p0 = blockIdx.x * 32, c0 = blockIdx.y * 32;
    int tx = threadIdx.x, ty = threadIdx.y;
    for (int i = ty; i < 32; i += 8)
        tile[i][tx] = T[((size_t)(b * CT + c0 + i)) * HW + p0 + tx];
    __syncthreads();
    for (int i = ty; i < 32; i += 8) {
        float v = tile[tx][i];
        __nv_bfloat16 h = __float2bfloat16(v);
        float hf = __bfloat162float(h);
        size_t o = ((size_t)b * HW + p0 + i) * CT + c0 + tx;
        g_Thi[o] = h;
        g_Tlo[o] = __float2bfloat16(v - hf);
    }
}

// weights split: W1[co][ci][tap] -> Whi/Wlo[tap][co][ci]
__global__ void wprep_kernel(const float* __restrict__ W1) {
    int idx = blockIdx.x * blockDim.x + threadIdx.x;
    if (idx >= 9 * CM * CT) return;
    int ci = idx & (CT - 1);
    int rest = idx >> 10;
    int co = rest & (CM - 1);
    int tap = rest >> 9;
    float w = W1[((size_t)co * CT + ci) * 9 + tap];
    __nv_bfloat16 h = __float2bfloat16(w);
    float hf = __bfloat162float(h);
    g_Whi[idx] = h;
    g_Wlo[idx] = __float2bfloat16(w - hf);
}

// conv1 via mma.sync bf16x3 implicit GEMM.
// CTA: 256 threads, 128 px x 128 co, SINGLE smem buffer; 2 CTAs/SM anti-phase.
#define ROWB 144                      // bytes per smem row (64 bf16 + 8 pad)
#define A_BYTES (128 * ROWB)          // 18432
#define STAGE_BYTES (4 * A_BYTES)     // Ahi,Alo,Bhi,Blo = 73728
__global__ __launch_bounds__(256, 2)
void convmma_kernel(const float* __restrict__ b1) {
    extern __shared__ char dsm[];
    uint32_t sb = smem_to_u32(dsm);
    int tid = threadIdx.x, lane = tid & 31, wid = tid >> 5;
    int co0 = blockIdx.x * 128;
    int pixtile = blockIdx.y;
    int bb = blockIdx.z;
    int y0 = pixtile * 2, p0 = pixtile * 128;
    int wm = wid & 3, wn = wid >> 2;   // wm: 4 M-groups of 32 px; wn: 2 N-groups of 64 co

    float acc[2][8][4];
#pragma unroll
    for (int i = 0; i < 2; ++i)
#pragma unroll
        for (int j = 0; j < 8; ++j)
#pragma unroll
            for (int k = 0; k < 4; ++k) acc[i][j][k] = 0.f;

    uint32_t Ah = sb, Al = sb + A_BYTES, Bh = sb + 2 * A_BYTES,
             Bl = sb + 3 * A_BYTES;

#pragma unroll 1
    for (int c = 0; c < 144; ++c) {
        int tap = c >> 4, kc = c & 15;
        int dy = tap / 3 - 1, dx = tap % 3 - 1;
        int ci0 = kc * 64;
        // ---- load chunk (single buffer) ----
        // A: 128 pixel rows x 64 ci, shifted + zero-masked
#pragma unroll
        for (int i = 0; i < 4; ++i) {
            int u = i * 256 + tid;
            int r = u >> 3, seg = u & 7;
            int ys = y0 + (r >> 6) + dy;
            int xs = (r & 63) + dx;
            bool ok = ((unsigned)ys < 64u) && ((unsigned)xs < 64u);
            int ysc = ok ? ys : 0, xsc = ok ? xs : 0;
            size_t g = ((size_t)(bb * HW + ysc * 64 + xsc)) * CT + ci0 + seg * 8;
            uint32_t off = (uint32_t)(r * ROWB + seg * 16);
            cp16(Ah + off, g_Thi + g, ok);
            cp16(Al + off, g_Tlo + g, ok);
        }
        // B: 128 co rows x 64 ci
#pragma unroll
        for (int i = 0; i < 4; ++i) {
            int u = i * 256 + tid;
            int r = u >> 3, seg = u & 7;
            size_t g = ((size_t)(tap * CM + co0 + r)) * CT + ci0 + seg * 8;
            uint32_t off = (uint32_t)(r * ROWB + seg * 16);
            cp16(Bh + off, g_Whi + g, true);
            cp16(Bl + off, g_Wlo + g, true);
        }
        CP_COMMIT();
        CP_WAIT0();
        __syncthreads();

        // ---- compute ----
#pragma unroll
        for (int ks = 0; ks < 4; ++ks) {
            uint32_t aH[2][4], aL[2][4];
#pragma unroll
            for (int t = 0; t < 2; ++t) {
                uint32_t ra = (uint32_t)((wm * 32 + t * 16 + (lane & 15)) * ROWB +
                                         ks * 32 + (lane >> 4) * 16);
                ldsm4(aH[t], Ah + ra);
                ldsm4(aL[t], Al + ra);
            }
#pragma unroll
            for (int nt = 0; nt < 4; ++nt) {
                uint32_t rb = (uint32_t)((wn * 64 + nt * 16 + (lane & 15)) * ROWB +
                                         ks * 32 + (lane >> 4) * 16);
                uint32_t bHf[4], bLf[4];
                ldsm4(bHf, Bh + rb);
                ldsm4(bLf, Bl + rb);
#pragma unroll
                for (int mi = 0; mi < 2; ++mi) {
                    mma16816(acc[mi][2 * nt], aH[mi], bHf[0], bHf[2]);
                    mma16816(acc[mi][2 * nt + 1], aH[mi], bHf[1], bHf[3]);
                    mma16816(acc[mi][2 * nt], aL[mi], bHf[0], bHf[2]);
                    mma16816(acc[mi][2 * nt + 1], aL[mi], bHf[1], bHf[3]);
                    mma16816(acc[mi][2 * nt], aH[mi], bLf[0], bLf[2]);
                    mma16816(acc[mi][2 * nt + 1], aH[mi], bLf[1], bLf[3]);
                }
            }
        }
        __syncthreads();   // buffer reuse guard
    }

    // epilogue: bias + relu -> g_h[b][co][p]
#pragma unroll
    for (int mi = 0; mi < 2; ++mi) {
        int r0 = wm * 32 + mi * 16 + (lane >> 2);
#pragma unroll
        for (int nt = 0; nt < 8; ++nt) {
            int co = co0 + wn * 64 + nt * 8 + (lane & 3) * 2;
            float bv0 = b1[co], bv1 = b1[co + 1];
            float* q0 = &g_h[((size_t)(bb * CM + co)) * HW];
            float* q1 = &g_h[((size_t)(bb * CM + co + 1)) * HW];
            q0[p0 + r0] = fmaxf(acc[mi][nt][0] + bv0, 0.f);
            q1[p0 + r0] = fmaxf(acc[mi][nt][1] + bv1, 0.f);
            q0[p0 + r0 + 8] = fmaxf(acc[mi][nt][2] + bv0, 0.f);
            q1[p0 + r0 + 8] = fmaxf(acc[mi][nt][3] + bv1, 0.f);
        }
    }
}

// 1x1 conv over 512 channels + softplus; writes heatmap to scratch and d_out+3.
__global__ void heat_kernel(const float* __restrict__ w2,
                            const float* __restrict__ b2, float* __restrict__ out) {
    int b = blockIdx.x;
    int p = blockIdx.y * 256 + threadIdx.x;
    float acc = b2[0];
    const float* hp = g_h + (size_t)b * CM * HW + p;
#pragma unroll 4
    for (int c = 0; c < CM; ++c) acc += hp[(size_t)c * HW] * w2[c];
    float sp = fmaxf(acc, 0.f) + log1pf(expf(-fabsf(acc)));
    g_heat[b * HW + p] = sp;
    out[3 + b * HW + p] = sp;
}

// per-batch: normalize to prob, add JAX (partitionable threefry) Gumbel -> score
__global__ void score_kernel() {
    __shared__ float sh[33];
    int b = blockIdx.x;
    float s = 0.f;
    for (int p = threadIdx.x; p < HW; p += 256) s += g_heat[b * HW + p];
    float S = block_sum_256(s, sh);
    for (int p = threadIdx.x; p < HW; p += 256) {
        unsigned gi = (unsigned)(b * HW + p);
        unsigned o0, o1;
        threefry2x32(0u, 42u, 0u, gi, o0, o1);
        unsigned bits = o0 ^ o1;
        float f = __uint_as_float((bits >> 9) | 0x3f800000u) - 1.0f;
        float u = fmaxf(1e-8f, f * (1.0f - 1e-8f) + 1e-8f);
        float gum = -logf(-logf(u));
        g_score[gi] = logf(g_heat[gi] / (S + 1e-6f) + 1e-12f) + gum;
    }
}

// top-256 per batch via in-smem bitonic sort
__global__ void topk_kernel() {
    __shared__ float key[HW];
    __shared__ int val[HW];
    int b = blockIdx.x;
    for (int i = threadIdx.x; i < HW; i += blockDim.x) {
        key[i] = -g_score[b * HW + i];
        val[i] = i;
    }
    for (int k = 2; k <= HW; k <<= 1)
        for (int j = k >> 1; j > 0; j >>= 1) {
            __syncthreads();
            for (int i = threadIdx.x; i < HW; i += blockDim.x) {
                int p = i ^ j;
                if (p > i) {
                    bool up = ((i & k) == 0);
                    float ki = key[i], kp = key[p];
                    if ((ki > kp) == up) {
                        key[i] = kp;
                        key[p] = ki;
                        int t = val[i];
                        val[i] = val[p];
                        val[p] = t;
                    }
                }
            }
        }
    __syncthreads();
    for (int i = threadIdx.x; i < NA; i += blockDim.x) g_idx[b * NA + i] = val[i];
}

// bilinear sample == 0.25 * sum of 4 pixels with zero pad
__global__ void gather_kernel(const float* __restrict__ T,
                              const float* __restrict__ Sf) {
    int blk = blockIdx.x;
    int b = blk >> 8, n = blk & 255;
    int idx = g_idx[b * NA + n];
    int r = idx >> 6, c = idx & 63;
    bool rv = r > 0, cv = c > 0;
    int o11 = r * WW + c, o10 = o11 - 1, o01 = o11 - WW, o00 = o01 - 1;
    for (int ch = threadIdx.x; ch < CT; ch += blockDim.x) {
        const float* base = T + (size_t)(b * CT + ch) * HW;
        float s = base[o11];
        if (cv) s += base[o10];
        if (rv) {
            s += base[o01];
            if (cv) s += base[o00];
        }
        g_sampT[(size_t)(b * NA + n) * CT + ch] = 0.25f * s;
    }
    for (int ch = threadIdx.x; ch < CS; ch += blockDim.x) {
        const float* base = Sf + (size_t)(b * CS + ch) * HW;
        float s = base[o11];
        if (cv) s += base[o10];
        if (rv) {
            s += base[o01];
            if (cv) s += base[o00];
        }
        g_sampS[(size_t)(b * NA + n) * CS + ch] = 0.25f * s;
    }
    if (threadIdx.x == 0) {
        const float* base = g_heat + b * HW;
        float s = base[o11];
        if (cv) s += base[o10];
        if (rv) {
            s += base[o01];
            if (cv) s += base[o00];
        }
        g_sal[b * NA + n] = 0.25f * s;
    }
}

// [rows,C]@[C,256] + bias -> LayerNorm -> l2norm. 8 rows per block, thread = p.
template <int C>
__global__ void proj_kernel(const float* __restrict__ wmat,
                            const float* __restrict__ bias,
                            const float* __restrict__ gamma,
                            const float* __restrict__ beta) {
    __shared__ float sRow[8 * C];
    __shared__ float sh[33];
    const float* samp = (C == CT) ? g_sampT : g_sampS;
    float* outp = (C == CT) ? g_ft : g_fs;
    int a0 = blockIdx.x * 8;
    int p = threadIdx.x;
    for (int i = threadIdx.x; i < 8 * C; i += 256) sRow[i] = samp[(size_t)a0 * C + i];
    __syncthreads();
    float acc[8];
#pragma unroll
    for (int i = 0; i < 8; ++i) acc[i] = 0.f;
    for (int c = 0; c < C; ++c) {
        float w = wmat[(size_t)c * NP + p];
#pragma unroll
        for (int i = 0; i < 8; ++i) acc[i] += sRow[i * C + c] * w;
    }
    float bi = bias[p], ga = gamma[p], be = beta[p];
#pragma unroll 1
    for (int i = 0; i < 8; ++i) {
        float x = acc[i] + bi;
        float mu = block_sum_256(x, sh) * (1.0f / NP);
        float d = x - mu;
        float var = block_sum_256(d * d, sh) * (1.0f / NP);
        float y = d * rsqrtf(var + 1e-5f) * ga + be;
        float nrm = sqrtf(block_sum_256(y * y, sh));
        y = y / fmaxf(nrm, 1e-12f);
        outp[(size_t)(a0 + i) * NP + p] = y;
    }
}

__global__ void gafd_kernel() {
    __shared__ float sh[33];
    float s = 0.f;
    const int total = NB * NA * NP;
    for (int i = blockIdx.x * blockDim.x + threadIdx.x; i < total;
         i += gridDim.x * blockDim.x) {
        float d = g_fs[i] - g_ft[i];
        s += d * d;
    }
    float bs = block_sum_256(s, sh);
    if (threadIdx.x == 0) atomicAdd(&g_gafd, bs);
}

__global__ void bd_kernel() {
    __shared__ float sh[33];
    int b = blockIdx.x;
    float s = g_sal[b * NA + threadIdx.x];
    float mx = block_max_256(s, sh);
    int bd = (s > 0.6f * mx) ? 1 : 0;
    g_bd[b * NA + threadIdx.x] = bd;
    float cnt = block_sum_256((float)bd, sh);
    if (threadIdx.x == 0) g_cnt[b] = (int)(cnt + 0.5f);
}

__global__ void abcd_kernel() {
    __shared__ float fsn[NP];
    __shared__ float sh[33];
    int blk = blockIdx.x;
    int b = blk >> 8, n = blk & 255;
    if (!g_bd[b * NA + n]) return;
    int t = threadIdx.x;
    float fv = g_fs[(size_t)(b * NA + n) * NP + t];
    float ftv = g_ft[(size_t)(b * NA + n) * NP + t];
    fsn[t] = fv;
    __syncthreads();
    float pos = block_sum_256(fv * ftv, sh) * 10.0f;  // /TAU
    const float4* fm = (const float4*)(g_fs + (size_t)(b * NA + t) * NP);
    float dm = 0.f;
#pragma unroll 4
    for (int q = 0; q < NP / 4; ++q) {
        float4 v = fm[q];
        dm += fsn[4 * q] * v.x + fsn[4 * q + 1] * v.y + fsn[4 * q + 2] * v.z +
              fsn[4 * q + 3] * v.w;
    }
    float val = g_bd[b * NA + t] ? -1e30f : dm * 10.0f;
    float mx = fmaxf(pos, block_max_256(val, sh));
    float e = (val < -1e29f) ? 0.f : expf(val - mx);
    float ssum = block_sum_256(e, sh) + expf(pos - mx);
    if (t == 0) atomicAdd(&g_abcd_b[b], mx + logf(ssum) - pos);
}

__global__ void final_kernel(float* __restrict__ out) {
    int t = threadIdx.x;
    float per = 0.f, valid = 0.f;
    if (t < NB) {
        int c = g_cnt[t];
        per = g_abcd_b[t] / fmaxf((float)c, 1.0f);
        valid = (c > 0 && c < NA) ? 1.0f : 0.0f;
    }
    float pv = per * valid;
#pragma unroll
    for (int o = 16; o; o >>= 1) {
        pv += __shfl_down_sync(0xffffffffu, pv, o);
        valid += __shfl_down_sync(0xffffffffu, valid, o);
    }
    if (t == 0) {
        float gafd = g_gafd * (1.0f / (NB * NA * NP));
        float abcd = (valid > 0.f) ? pv / valid : 0.f;
        out[0] = gafd + 0.5f * abcd;
        out[1] = gafd;
        out[2] = abcd;
    }
}

// ---------------- host launch ----------------
extern "C" void kernel_launch(void* const* d_in, const int* in_sizes, int n_in,
                              void* d_out, int out_size) {
    const float* T = (const float*)d_in[0];
    const float* Sf = (const float*)d_in[1];
    const float* w1 = (const float*)d_in[2];
    const float* b1 = (const float*)d_in[3];
    const float* w2 = (const float*)d_in[4];
    const float* b2 = (const float*)d_in[5];
    const float* tw = (const float*)d_in[6];
    const float* tb = (const float*)d_in[7];
    const float* tg = (const float*)d_in[8];
    const float* tbe = (const float*)d_in[9];
    const float* sw = (const float*)d_in[10];
    const float* sb = (const float*)d_in[11];
    const float* sg = (const float*)d_in[12];
    const float* sbe = (const float*)d_in[13];
    float* out = (float*)d_out;

    const int DSMEM = STAGE_BYTES;  // 73728 per CTA, 2 CTAs/SM
    static int s_attr_done = 0;
    if (!s_attr_done) {
        cudaFuncSetAttribute(convmma_kernel,
                             cudaFuncAttributeMaxDynamicSharedMemorySize, DSMEM);
        s_attr_done = 1;
    }

    reset_kernel<<<1, 32>>>();
    tprep_kernel<<<dim3(128, 32, 16), dim3(32, 8)>>>(T);
    wprep_kernel<<<(9 * CM * CT + 255) / 256, 256>>>(w1);
    convmma_kernel<<<dim3(4, 32, 16), 256, DSMEM>>>(b1);
    heat_kernel<<<dim3(16, 16), 256>>>(w2, b2, out);
    score_kernel<<<16, 256>>>();
    topk_kernel<<<16, 512>>>();
    gather_kernel<<<NB * NA, 256>>>(T, Sf);
    proj_kernel<CT><<<512, 256>>>(tw, tb, tg, tbe);
    proj_kernel<CS><<<512, 256>>>(sw, sb, sg, sbe);
    gafd_kernel<<<256, 256>>>();
    bd_kernel<<<NB, 256>>>();
    abcd_kernel<<<NB * NA, 256>>>();
    final_kernel<<<1, 32>>>(out);
}